// round 7
// baseline (speedup 1.0000x reference)
#include <cuda_runtime.h>

// B=64, T=512, E=8192
// out[b][j] = (1/count) * sum_{r=r0}^{511} x[b*T*E + (j+512) + r*8191]
//   r0 = max(0, j - 7679), count = 512 - r0, j in [0, 8190].
//
// Hot path uses ALIGNED float4 loads despite the stride 8191 (== 3 mod 4):
// the misalignment phase p = (3r) & 3 is periodic in r with period 4, so we
// unroll r by 4 and pick the 4 needed lanes from two aligned float4s with
// compile-time register selects. 4x bytes per outstanding load entry.

#define B_DIM 64
#define T_DIM 512
#define E_DIM 8192
#define OUT_COLS (E_DIM - 1)          // 8191
#define ROW_STRIDE (E_DIM - 1)        // 8191
#define J_FULL (E_DIM - T_DIM - 1)    // 7679
#define BLOCK 128
#define TILE_W (BLOCK * 4)            // 512 j per CTA, 4 per thread
#define NUM_TILES (E_DIM / TILE_W)    // 16; last tile is the ragged tail

__global__ __launch_bounds__(BLOCK) void antidiag_mean_kernel(
    const float* __restrict__ x, float* __restrict__ out)
{
    const int tid = threadIdx.x;
    const int b   = blockIdx.y;
    const int j0  = blockIdx.x * TILE_W;

    const float* __restrict__ xb = x + (size_t)b * T_DIM * E_DIM;
    float* __restrict__ ob = out + (size_t)b * OUT_COLS;

    if (blockIdx.x < NUM_TILES - 1) {
        // ---- hot path: 4 consecutive j per thread, full count = 512 ----
        const int jb = j0 + 4 * tid;                 // output j base
        const float* pb = xb + (jb + T_DIM);         // 16B-aligned (jb%4==0, +512)

        float a0 = 0.f, a1 = 0.f, a2 = 0.f, a3 = 0.f;

        #pragma unroll 1
        for (int rg = 0; rg < T_DIM; rg += 4) {
            const unsigned off = (unsigned)(rg * ROW_STRIDE);
            const float* gp = pb + off;

            // r = rg     : phase 0 -> one aligned float4, lanes 0..3
            {
                float4 q = *reinterpret_cast<const float4*>(gp);
                a0 += q.x; a1 += q.y; a2 += q.z; a3 += q.w;
            }
            // r = rg + 1 : A = off+8191, phase 3, L = off+8188
            {
                float4 q0 = *reinterpret_cast<const float4*>(gp + 8188u);
                float4 q1 = *reinterpret_cast<const float4*>(gp + 8192u);
                a0 += q0.w; a1 += q1.x; a2 += q1.y; a3 += q1.z;
            }
            // r = rg + 2 : A = off+16382, phase 2, L = off+16380
            {
                float4 q0 = *reinterpret_cast<const float4*>(gp + 16380u);
                float4 q1 = *reinterpret_cast<const float4*>(gp + 16384u);
                a0 += q0.z; a1 += q0.w; a2 += q1.x; a3 += q1.y;
            }
            // r = rg + 3 : A = off+24573, phase 1, L = off+24572
            {
                float4 q0 = *reinterpret_cast<const float4*>(gp + 24572u);
                float4 q1 = *reinterpret_cast<const float4*>(gp + 24576u);
                a0 += q0.y; a1 += q0.z; a2 += q0.w; a3 += q1.x;
            }
        }

        const float inv = 1.0f / (float)T_DIM;
        ob[jb + 0] = a0 * inv;
        ob[jb + 1] = a1 * inv;
        ob[jb + 2] = a2 * inv;
        ob[jb + 3] = a3 * inv;
    } else {
        // ---- tail tile (j in [7680, 8190]): ragged counts, scalar path ----
        #pragma unroll
        for (int k = 0; k < 4; ++k) {
            const int j = j0 + 4 * tid + k;
            if (j >= OUT_COLS) continue;
            const int r0 = (j > J_FULL) ? (j - J_FULL) : 0;
            const float* p = xb + (j + T_DIM);
            float s = 0.0f;
            #pragma unroll 8
            for (int r = r0; r < T_DIM; ++r)
                s += p[(unsigned)(r * ROW_STRIDE)];
            ob[j] = s * (1.0f / (float)(T_DIM - r0));
        }
    }
}

extern "C" void kernel_launch(void* const* d_in, const int* in_sizes, int n_in,
                              void* d_out, int out_size)
{
    const float* x = (const float*)d_in[0];
    float* out = (float*)d_out;

    dim3 block(BLOCK);
    dim3 grid(NUM_TILES, B_DIM);   // 16 x 64 = 1024 CTAs
    antidiag_mean_kernel<<<grid, block>>>(x, out);
}

// round 8
// speedup vs baseline: 1.3928x; 1.3928x over previous
#include <cuda_runtime.h>

// B=64, T=512, E=8192
// out[b][j] = (1/count) * sum_{r=r0}^{511} x[b*T*E + (j+512) + r*8191]
//   r0 = max(0, j - 7679), count = 512 - r0, j in [0, 8190].

#define B_DIM 64
#define T_DIM 512
#define E_DIM 8192
#define OUT_COLS (E_DIM - 1)          // 8191
#define ROW_STRIDE (E_DIM - 1)        // 8191
#define J_FULL (E_DIM - T_DIM - 1)    // 7679
#define BLOCK 256
#define NUM_TILES (E_DIM / BLOCK)     // 32 j-tiles of 256
#define FULL_TILES 30                 // tiles 0..29 end at j=7679 (full count)
#define R_Q (T_DIM / 4)               // 128
#define Q_OFF ((unsigned)(R_Q * ROW_STRIDE))   // quarter stride in floats

__global__ __launch_bounds__(BLOCK, 8) void antidiag_mean_kernel(
    const float* __restrict__ x, float* __restrict__ out)
{
    const int tid = threadIdx.x;
    const int b   = blockIdx.y;
    const int j   = blockIdx.x * BLOCK + tid;

    const float* __restrict__ xb = x + (size_t)b * T_DIM * E_DIM;
    float* __restrict__ ob = out + (size_t)b * OUT_COLS;

    if (blockIdx.x < FULL_TILES) {
        // ---- hot path: full count = 512, 4 independent r-quarter streams ----
        const float* p = xb + (j + T_DIM);
        float s0 = 0.f, s1 = 0.f, s2 = 0.f, s3 = 0.f;
        // unroll 8 x 4 streams -> 32 independent LDGs per scoreboard window.
        // 32-bit offsets: max byte offset < 16.8MB < 2^31.
        #pragma unroll 8
        for (int r = 0; r < R_Q; ++r) {
            const unsigned off = (unsigned)(r * ROW_STRIDE);
            s0 += p[off];
            s1 += p[off + Q_OFF];
            s2 += p[off + 2u * Q_OFF];
            s3 += p[off + 3u * Q_OFF];
        }
        ob[j] = ((s0 + s1) + (s2 + s3)) * (1.0f / (float)T_DIM);
    } else {
        // ---- ragged tiles (j in [7680, 8190]) ----
        if (j >= OUT_COLS) return;
        const int r0 = j - J_FULL;     // >= 1 here
        const float* p = xb + (j + T_DIM);
        float s = 0.0f;
        #pragma unroll 8
        for (int r = r0; r < T_DIM; ++r)
            s += p[(unsigned)(r * ROW_STRIDE)];
        ob[j] = s * (1.0f / (float)(T_DIM - r0));
    }
}

extern "C" void kernel_launch(void* const* d_in, const int* in_sizes, int n_in,
                              void* d_out, int out_size)
{
    const float* x = (const float*)d_in[0];
    float* out = (float*)d_out;

    dim3 block(BLOCK);
    dim3 grid(NUM_TILES, B_DIM);   // 32 x 64 = 2048 CTAs
    antidiag_mean_kernel<<<grid, block>>>(x, out);
}

// round 9
// speedup vs baseline: 1.4914x; 1.0708x over previous
#include <cuda_runtime.h>

// B=64, T=512, E=8192
// out[b][j] = (1/count) * sum_{r=r0}^{511} x[b*T*E + (j+512) + r*8191]
//   r0 = max(0, j - 7679), count = 512 - r0, j in [0, 8190].
//
// Two-phase: phase 1 computes partial sums over 4 r-quarters (8192 uniform
// CTAs -> ~7 full waves, amortizing the drain tail); phase 2 combines.

#define B_DIM 64
#define T_DIM 512
#define E_DIM 8192
#define OUT_COLS (E_DIM - 1)          // 8191
#define ROW_STRIDE (E_DIM - 1)        // 8191
#define J_FULL (E_DIM - T_DIM - 1)    // 7679
#define BLOCK 256
#define JTILES (E_DIM / BLOCK)        // 32
#define FULL_TILES 30                 // tiles 0..29: j <= 7679 (full count)
#define NQ 4
#define R_Q (T_DIM / NQ)              // 128 rows per quarter
#define R_H (R_Q / 2)                 // 64 rows per stream
#define H_OFF ((unsigned)(R_H * ROW_STRIDE))

// Partial sums: [q][b][j] (8 MB scratch)
__device__ float g_part[NQ * B_DIM * E_DIM];

__global__ __launch_bounds__(BLOCK, 8) void antidiag_partial_kernel(
    const float* __restrict__ x)
{
    const int tid = threadIdx.x;
    const int b   = blockIdx.y;
    const int q   = blockIdx.z;
    const int j   = blockIdx.x * BLOCK + tid;
    if (j >= OUT_COLS) return;

    const float* __restrict__ p =
        x + (size_t)b * T_DIM * E_DIM + (size_t)(j + T_DIM);
    const int rbeg = q * R_Q;

    float s = 0.0f;
    if (blockIdx.x < FULL_TILES) {
        // hot path: full quarter, two 64-row streams, unroll 8 -> 16-LDG window
        const float* ph = p + (size_t)rbeg * ROW_STRIDE;
        float s0 = 0.f, s1 = 0.f;
        #pragma unroll 8
        for (int r = 0; r < R_H; ++r) {
            const unsigned off = (unsigned)(r * ROW_STRIDE);
            s0 += ph[off];
            s1 += ph[off + H_OFF];
        }
        s = s0 + s1;
    } else {
        // ragged tail (j in [7680, 8190]): clamp quarter start to r0
        const int r0 = j - J_FULL;               // >= 1 here
        const int rs = (r0 > rbeg) ? r0 : rbeg;
        const int re = rbeg + R_Q;
        #pragma unroll 8
        for (int r = rs; r < re; ++r)
            s += p[(unsigned)(r * ROW_STRIDE)];
    }

    g_part[((size_t)q * B_DIM + b) * E_DIM + j] = s;
}

__global__ __launch_bounds__(BLOCK) void antidiag_combine_kernel(
    float* __restrict__ out)
{
    const int tid = threadIdx.x;
    const int b   = blockIdx.y;
    const int j   = blockIdx.x * BLOCK + tid;
    if (j >= OUT_COLS) return;

    float s = 0.0f;
    #pragma unroll
    for (int q = 0; q < NQ; ++q)
        s += g_part[((size_t)q * B_DIM + b) * E_DIM + j];

    const int r0 = (j > J_FULL) ? (j - J_FULL) : 0;
    out[(size_t)b * OUT_COLS + j] = s * (1.0f / (float)(T_DIM - r0));
}

extern "C" void kernel_launch(void* const* d_in, const int* in_sizes, int n_in,
                              void* d_out, int out_size)
{
    const float* x = (const float*)d_in[0];
    float* out = (float*)d_out;

    dim3 block(BLOCK);
    dim3 grid1(JTILES, B_DIM, NQ);   // 32 x 64 x 4 = 8192 CTAs
    antidiag_partial_kernel<<<grid1, block>>>(x);

    dim3 grid2(JTILES, B_DIM);       // 32 x 64 = 2048 CTAs
    antidiag_combine_kernel<<<grid2, block>>>(out);
}